// round 10
// baseline (speedup 1.0000x reference)
#include <cuda_runtime.h>
#include <mma.h>
#include <math.h>
#include <cstdint>

using namespace nvcuda;

#define NBATCH 8
#define T0C    8192
#define INCH   256
#define HIDC   128
#define MIDC   512
#define OUTC   256
#define NL     20
#define TGT    6146
#define RST    8192

// ---- wmma tile ld's ----
#define XLD    68     // input conv X ld
#define WLDI   136
#define HLD    36
#define W1LD   520
#define W2LD   264

// ---- layer kernel geometry ----
#define LXL    132    // layer X tile ld (256 rows x 128 cols + pad)
#define LW1    264    // GEMM1 weight chunk ld (16 x 256)
#define LW2    136    // GEMM2 weight chunk ld (16 x 128)
#define WBUF   4224   // floats per weight buffer (16*264)

typedef wmma::fragment<wmma::matrix_a, 16, 16, 8, wmma::precision::tf32, wmma::col_major> FragA;
typedef wmma::fragment<wmma::matrix_b, 16, 16, 8, wmma::precision::tf32, wmma::row_major> FragB;
typedef wmma::fragment<wmma::accumulator, 16, 16, 8, float> FragC;

// ---------------- device scratch ----------------
__device__ float g_res0[(size_t)NBATCH * HIDC * RST];
__device__ float g_res1[(size_t)NBATCH * HIDC * RST];
__device__ float g_final[(size_t)NBATCH * HIDC * TGT];
__device__ float g_WA[(size_t)NL * 256 * 256];   // tf32 [l][k][row], rows 0..127=f, 128..255=g
__device__ float g_WR[(size_t)NL * HIDC * HIDC]; // tf32 [l][k][o]
__device__ float g_WiP[INCH * HIDC];
__device__ float g_W1P[HIDC * MIDC];
__device__ float g_W2P[MIDC * OUTC];

// ---------------- cp.async helpers (baseline sm_80+, OK on compute_103) ----------------
__device__ __forceinline__ uint32_t smem_u32(const void* p) {
    uint32_t a;
    asm("{ .reg .u64 t; cvta.to.shared.u64 t, %1; cvt.u32.u64 %0, t; }" : "=r"(a) : "l"(p));
    return a;
}
#define CP_ASYNC16(dst, src) \
    asm volatile("cp.async.cg.shared.global [%0], [%1], 16;" :: "r"(dst), "l"(src) : "memory")
#define CP_COMMIT() asm volatile("cp.async.commit_group;" ::: "memory")
#define CP_WAIT1()  asm volatile("cp.async.wait_group 1;" ::: "memory")

// ---------------- weight packing (fp32 -> tf32, transposed) ----------------
__global__ void pack_fg(const float* __restrict__ Wf, const float* __restrict__ Wg) {
    int i = blockIdx.x * 256 + threadIdx.x;
    if (i >= NL * 256 * 256) return;
    int row = i & 255;
    int k   = (i >> 8) & 255;
    int l   = i >> 16;
    const float* W = (row < 128) ? Wf : Wg;
    int o = row & 127;
    g_WA[i] = wmma::__float_to_tf32(W[(((size_t)l * 128 + o) * 128 + (k & 127)) * 2 + (k >> 7)]);
}
__global__ void pack_r(const float* __restrict__ Wr) {
    int i = blockIdx.x * 256 + threadIdx.x;
    if (i >= NL * 128 * 128) return;
    int o = i & 127;
    int k = (i >> 7) & 127;
    int l = i >> 14;
    g_WR[i] = wmma::__float_to_tf32(Wr[((size_t)l * 128 + o) * 128 + k]);
}
__global__ void pack_t(float* __restrict__ dst, const float* __restrict__ src, int O, int K) {
    int i = blockIdx.x * 256 + threadIdx.x;
    if (i >= O * K) return;
    int o = i % O;
    int k = i / O;
    dst[i] = wmma::__float_to_tf32(src[o * K + k]);
}

// ---------------- input 1x1 conv (wmma tf32) ----------------
__global__ __launch_bounds__(256)
void input_conv_k(const float* __restrict__ inp, const float* __restrict__ bi) {
    extern __shared__ float sm[];
    float* sX = sm;
    float* sW = sm + 256 * XLD;
    int b = blockIdx.y, t0 = blockIdx.x * 64, tid = threadIdx.x, wid = tid >> 5;
    const float* src = inp + (size_t)b * INCH * T0C;
    #pragma unroll 4
    for (int j = 0; j < 64; j++) {
        int idx = j * 256 + tid, row = idx >> 6, col = idx & 63;
        sX[row * XLD + col] = wmma::__float_to_tf32(src[(size_t)row * T0C + t0 + col]);
    }
    int wM = wid >> 1, wN = wid & 1, m0 = wM * 32, n0 = wN * 32;
    FragC acc[2][2];
    #pragma unroll
    for (int i = 0; i < 2; i++)
        #pragma unroll
        for (int j = 0; j < 2; j++) wmma::fill_fragment(acc[i][j], 0.f);
    for (int k0 = 0; k0 < 256; k0 += 16) {
        __syncthreads();
        #pragma unroll
        for (int j = 0; j < 8; j++) {
            int idx = j * 256 + tid, kc = idx >> 7, r = idx & 127;
            sW[kc * WLDI + r] = g_WiP[(size_t)(k0 + kc) * 128 + r];
        }
        __syncthreads();
        #pragma unroll
        for (int ks = 0; ks < 2; ks++) {
            FragA a[2]; FragB bb[2];
            #pragma unroll
            for (int i = 0; i < 2; i++) wmma::load_matrix_sync(a[i], sW + ks * 8 * WLDI + m0 + i * 16, WLDI);
            #pragma unroll
            for (int j = 0; j < 2; j++) wmma::load_matrix_sync(bb[j], sX + (k0 + ks * 8) * XLD + n0 + j * 16, XLD);
            #pragma unroll
            for (int i = 0; i < 2; i++)
                #pragma unroll
                for (int j = 0; j < 2; j++) wmma::mma_sync(acc[i][j], a[i], bb[j], acc[i][j]);
        }
    }
    __syncthreads();
    #pragma unroll
    for (int i = 0; i < 2; i++)
        #pragma unroll
        for (int j = 0; j < 2; j++)
            wmma::store_matrix_sync(sX + (m0 + i * 16) * XLD + n0 + j * 16, acc[i][j], XLD, wmma::mem_row_major);
    __syncthreads();
    float* dst = g_res0 + (size_t)b * HIDC * RST;
    #pragma unroll 4
    for (int j = 0; j < 32; j++) {
        int idx = j * 256 + tid, row = idx >> 6, col = idx & 63;
        dst[(size_t)row * RST + t0 + col] = sX[row * XLD + col] + bi[row];
    }
}

// ---------------- fused residual layer (wmma tf32, cp.async-pipelined) ----------------
// 512 threads, 128 timesteps/block.
// GEMM1: D1[r, t] = sum_k WA[k, r] * X[k, t], M=256 (f||g), N=128, K=256.
// GEMM2: D2[o, t] = sum_k WR[k, o] * act[k, t], M=128, N=128, K=128.
__global__ __launch_bounds__(512)
void layer_w2(const float* __restrict__ rin, float* __restrict__ rout,
              const float* __restrict__ bf, const float* __restrict__ bg,
              const float* __restrict__ br,
              int l, int d, int Tin, int Tout, int first) {
    extern __shared__ float sm[];
    float* sX  = sm;                    // 256 x LXL
    float* sWb = sm + 256 * LXL;        // 3 x WBUF

    int b = blockIdx.y, t0 = blockIdx.x * 128, tid = threadIdx.x;
    int w = tid >> 5, wM = w >> 2, wN = w & 3;
    const float* src = rin + (size_t)b * HIDC * RST;

    const float* WAl = g_WA + (size_t)l * 65536;
    const float* WRl = g_WR + (size_t)l * 16384;

    uint32_t wbu[3];
    #pragma unroll
    for (int q = 0; q < 3; q++) wbu[q] = smem_u32(sWb + q * WBUF);

    // --- prefetch GEMM1 weight chunks 0,1 (cp.async overlaps X staging) ---
    #pragma unroll
    for (int c = 0; c < 2; c++) {
        const float* srcw = WAl + c * 16 * 256;
        #pragma unroll
        for (int q = 0; q < 2; q++) {
            int j = q * 512 + tid;
            int kc = j >> 6, r4 = (j & 63) * 4;
            CP_ASYNC16(wbu[c] + (uint32_t)(kc * LW1 + r4) * 4u, srcw + kc * 256 + r4);
        }
        CP_COMMIT();
    }

    // --- stage X (tf32): rows k<128 -> res[k, t], rows k>=128 -> res[k-128, t+d] ---
    #pragma unroll 4
    for (int it = 0; it < 64; it++) {
        int idx = it * 512 + tid;
        int row = idx >> 7, col = idx & 127;
        int ch = row & 127;
        int tt = t0 + col + ((row >= 128) ? d : 0);
        float v = (tt < Tin) ? src[(size_t)ch * RST + tt] : 0.f;
        sX[row * LXL + col] = wmma::__float_to_tf32(v);
    }

    // --- GEMM1: 16 chunks of k=16, pipelined ---
    int m0 = wM * 64, n0 = wN * 32;
    FragC acc1[4][2];
    #pragma unroll
    for (int i = 0; i < 4; i++)
        #pragma unroll
        for (int j = 0; j < 2; j++) wmma::fill_fragment(acc1[i][j], 0.f);

    for (int c = 0; c < 16; c++) {
        CP_WAIT1();
        __syncthreads();       // chunk c visible to all; also covers X staging on c==0
        if (c + 2 < 16) {
            const float* srcw = WAl + (c + 2) * 16 * 256;
            uint32_t dstb = wbu[(c + 2) % 3];
            #pragma unroll
            for (int q = 0; q < 2; q++) {
                int j = q * 512 + tid;
                int kc = j >> 6, r4 = (j & 63) * 4;
                CP_ASYNC16(dstb + (uint32_t)(kc * LW1 + r4) * 4u, srcw + kc * 256 + r4);
            }
            CP_COMMIT();
        }
        float* sW = sWb + (c % 3) * WBUF;
        #pragma unroll
        for (int ks = 0; ks < 2; ks++) {
            FragA a[4]; FragB bb[2];
            #pragma unroll
            for (int i = 0; i < 4; i++) wmma::load_matrix_sync(a[i], sW + ks * 8 * LW1 + m0 + i * 16, LW1);
            #pragma unroll
            for (int j = 0; j < 2; j++) wmma::load_matrix_sync(bb[j], sX + (c * 16 + ks * 8) * LXL + n0 + j * 16, LXL);
            #pragma unroll
            for (int i = 0; i < 4; i++)
                #pragma unroll
                for (int j = 0; j < 2; j++) wmma::mma_sync(acc1[i][j], a[i], bb[j], acc1[i][j]);
        }
    }
    __syncthreads();     // all warps done reading sX as B
    #pragma unroll
    for (int i = 0; i < 4; i++)
        #pragma unroll
        for (int j = 0; j < 2; j++)
            wmma::store_matrix_sync(sX + (m0 + i * 16) * LXL + n0 + j * 16, acc1[i][j], LXL, wmma::mem_row_major);
    __syncthreads();

    // --- prefetch GEMM2 chunks 0,1 (overlaps activation math) ---
    #pragma unroll
    for (int c = 0; c < 2; c++) {
        int kc = tid >> 5, r4 = (tid & 31) * 4;
        CP_ASYNC16(wbu[c] + (uint32_t)(kc * LW2 + r4) * 4u, WRl + (c * 16 + kc) * 128 + r4);
        CP_COMMIT();
    }

    // --- activation: act[o][t] = tanh(f+bf)*sigmoid(g+bg), tf32, rows 0..127 in place ---
    const float* bfl = bf + l * 128;
    const float* bgl = bg + l * 128;
    #pragma unroll 4
    for (int it = 0; it < 32; it++) {
        int idx = it * 512 + tid;
        int o = idx >> 7, t = idx & 127;
        float f = tanhf(sX[o * LXL + t] + bfl[o]);
        float g = 1.f / (1.f + expf(-(sX[(128 + o) * LXL + t] + bgl[o])));
        sX[o * LXL + t] = wmma::__float_to_tf32(f * g);
    }
    __syncthreads();

    // --- GEMM2: 8 chunks of k=16, pipelined ---
    int m2 = wM * 32, n2 = wN * 32;
    FragC acc2[2][2];
    #pragma unroll
    for (int i = 0; i < 2; i++)
        #pragma unroll
        for (int j = 0; j < 2; j++) wmma::fill_fragment(acc2[i][j], 0.f);

    for (int c = 0; c < 8; c++) {
        CP_WAIT1();
        __syncthreads();
        if (c + 2 < 8) {
            int kc = tid >> 5, r4 = (tid & 31) * 4;
            CP_ASYNC16(wbu[(c + 2) % 3] + (uint32_t)(kc * LW2 + r4) * 4u,
                       WRl + ((c + 2) * 16 + kc) * 128 + r4);
            CP_COMMIT();
        }
        float* sW = sWb + (c % 3) * WBUF;
        #pragma unroll
        for (int ks = 0; ks < 2; ks++) {
            FragA a[2]; FragB bb[2];
            #pragma unroll
            for (int i = 0; i < 2; i++) wmma::load_matrix_sync(a[i], sW + ks * 8 * LW2 + m2 + i * 16, LW2);
            #pragma unroll
            for (int j = 0; j < 2; j++) wmma::load_matrix_sync(bb[j], sX + (c * 16 + ks * 8) * LXL + n2 + j * 16, LXL);
            #pragma unroll
            for (int i = 0; i < 2; i++)
                #pragma unroll
                for (int j = 0; j < 2; j++) wmma::mma_sync(acc2[i][j], a[i], bb[j], acc2[i][j]);
        }
    }
    // stores target rows 128..255; GEMM2 B-frags only read rows 0..127 -> no pre-barrier needed
    #pragma unroll
    for (int i = 0; i < 2; i++)
        #pragma unroll
        for (int j = 0; j < 2; j++)
            wmma::store_matrix_sync(sX + (128 + m2 + i * 16) * LXL + n2 + j * 16, acc2[i][j], LXL, wmma::mem_row_major);
    __syncthreads();

    // --- epilogue (fp32): residual add re-reads src from global (L2 hit), skip accumulate ---
    const float* brl = br + l * 128;
    float* dst = rout + (size_t)b * HIDC * RST;
    float* fin = g_final + (size_t)b * HIDC * TGT;
    int off = Tout - TGT;
    #pragma unroll 4
    for (int it = 0; it < 32; it++) {
        int idx = it * 512 + tid;
        int o = idx >> 7, col = idx & 127;
        int t = t0 + col;
        if (t < Tout) {
            float xv = sX[(128 + o) * LXL + col] + brl[o];
            dst[(size_t)o * RST + t] = xv + src[(size_t)o * RST + t + d];
            int tf = t - off;
            if (tf >= 0) {
                float* p = &fin[(size_t)o * TGT + tf];
                *p = first ? xv : (*p + xv);
            }
        }
    }
}

// ---------------- head (wmma tf32) ----------------
__global__ __launch_bounds__(256)
void head_k(const float* __restrict__ b1, const float* __restrict__ b2,
            float* __restrict__ out) {
    extern __shared__ float sm[];
    float* sF = sm;
    float* sH = sm + 128 * HLD;
    float* sW = sm + 128 * HLD + 512 * HLD;
    int b = blockIdx.y, t0 = blockIdx.x * 32, tid = threadIdx.x, wid = tid >> 5;
    const float* fin = g_final + (size_t)b * HIDC * TGT;
    #pragma unroll
    for (int j = 0; j < 16; j++) {
        int idx = j * 256 + tid, row = idx >> 5, col = idx & 31;
        int t = t0 + col;
        float v = (t < TGT) ? fmaxf(fin[(size_t)row * TGT + t], 0.f) : 0.f;
        sF[row * HLD + col] = wmma::__float_to_tf32(v);
    }
    FragC a1[4][2];
    #pragma unroll
    for (int i = 0; i < 4; i++)
        #pragma unroll
        for (int j = 0; j < 2; j++) wmma::fill_fragment(a1[i][j], 0.f);
    for (int k0 = 0; k0 < 128; k0 += 16) {
        __syncthreads();
        #pragma unroll
        for (int j = 0; j < 32; j++) {
            int idx = j * 256 + tid, kc = idx >> 9, r = idx & 511;
            sW[kc * W1LD + r] = g_W1P[(size_t)(k0 + kc) * 512 + r];
        }
        __syncthreads();
        #pragma unroll
        for (int ks = 0; ks < 2; ks++) {
            FragA a[4]; FragB bb[2];
            #pragma unroll
            for (int i = 0; i < 4; i++) wmma::load_matrix_sync(a[i], sW + ks * 8 * W1LD + wid * 64 + i * 16, W1LD);
            #pragma unroll
            for (int j = 0; j < 2; j++) wmma::load_matrix_sync(bb[j], sF + (k0 + ks * 8) * HLD + j * 16, HLD);
            #pragma unroll
            for (int i = 0; i < 4; i++)
                #pragma unroll
                for (int j = 0; j < 2; j++) wmma::mma_sync(a1[i][j], a[i], bb[j], a1[i][j]);
        }
    }
    #pragma unroll
    for (int i = 0; i < 4; i++)
        #pragma unroll
        for (int j = 0; j < 2; j++)
            wmma::store_matrix_sync(sH + (wid * 64 + i * 16) * HLD + j * 16, a1[i][j], HLD, wmma::mem_row_major);
    __syncthreads();
    #pragma unroll
    for (int j = 0; j < 64; j++) {
        int idx = j * 256 + tid, r = idx >> 5, c = idx & 31;
        sH[r * HLD + c] = wmma::__float_to_tf32(fmaxf(sH[r * HLD + c] + b1[r], 0.f));
    }
    __syncthreads();
    FragC a2[2][2];
    #pragma unroll
    for (int i = 0; i < 2; i++)
        #pragma unroll
        for (int j = 0; j < 2; j++) wmma::fill_fragment(a2[i][j], 0.f);
    for (int k0 = 0; k0 < 512; k0 += 16) {
        __syncthreads();
        #pragma unroll
        for (int j = 0; j < 16; j++) {
            int idx = j * 256 + tid, kc = idx >> 8, r = idx & 255;
            sW[kc * W2LD + r] = g_W2P[(size_t)(k0 + kc) * 256 + r];
        }
        __syncthreads();
        #pragma unroll
        for (int ks = 0; ks < 2; ks++) {
            FragA a[2]; FragB bb[2];
            #pragma unroll
            for (int i = 0; i < 2; i++) wmma::load_matrix_sync(a[i], sW + ks * 8 * W2LD + wid * 32 + i * 16, W2LD);
            #pragma unroll
            for (int j = 0; j < 2; j++) wmma::load_matrix_sync(bb[j], sH + (k0 + ks * 8) * HLD + j * 16, HLD);
            #pragma unroll
            for (int i = 0; i < 2; i++)
                #pragma unroll
                for (int j = 0; j < 2; j++) wmma::mma_sync(a2[i][j], a[i], bb[j], a2[i][j]);
        }
    }
    __syncthreads();
    #pragma unroll
    for (int i = 0; i < 2; i++)
        #pragma unroll
        for (int j = 0; j < 2; j++)
            wmma::store_matrix_sync(sW + (wid * 32 + i * 16) * 32 + j * 16, a2[i][j], 32, wmma::mem_row_major);
    __syncthreads();
    #pragma unroll
    for (int j = 0; j < 32; j++) {
        int idx = j * 256 + tid, o = idx & 255, c = idx >> 8;
        int t = t0 + c;
        if (t < TGT)
            out[((size_t)b * TGT + t) * 256 + o] = sW[o * 32 + c] + b2[o];
    }
}

// ---------------- launch ----------------
static const int DIL[NL] = {1, 2, 4, 8, 16, 32, 64, 128, 256, 512,
                            1, 2, 4, 8, 16, 32, 64, 128, 256, 512};

extern "C" void kernel_launch(void* const* d_in, const int* in_sizes, int n_in,
                              void* d_out, int out_size) {
    const float* inputs = (const float*)d_in[0];
    const float* Wi = (const float*)d_in[1];
    const float* bi = (const float*)d_in[2];
    const float* Wf = (const float*)d_in[3];
    const float* bf = (const float*)d_in[4];
    const float* Wg = (const float*)d_in[5];
    const float* bg = (const float*)d_in[6];
    const float* Wr = (const float*)d_in[7];
    const float* br = (const float*)d_in[8];
    const float* W1 = (const float*)d_in[9];
    const float* b1 = (const float*)d_in[10];
    const float* W2 = (const float*)d_in[11];
    const float* b2 = (const float*)d_in[12];
    float* out = (float*)d_out;

    float *p_res0, *p_res1, *p_wip, *p_w1p, *p_w2p;
    cudaGetSymbolAddress((void**)&p_res0, g_res0);
    cudaGetSymbolAddress((void**)&p_res1, g_res1);
    cudaGetSymbolAddress((void**)&p_wip, g_WiP);
    cudaGetSymbolAddress((void**)&p_w1p, g_W1P);
    cudaGetSymbolAddress((void**)&p_w2p, g_W2P);

    const int SMEM_IC = (256 * XLD + 16 * WLDI) * 4;                 // 78336
    const int SMEM_LY = (256 * LXL + 3 * WBUF) * 4;                  // 185856
    const int SMEM_HD = (128 * HLD + 512 * HLD + 256 * 36) * 4;      // 129024

    cudaFuncSetAttribute(input_conv_k, cudaFuncAttributeMaxDynamicSharedMemorySize, SMEM_IC);
    cudaFuncSetAttribute(layer_w2,     cudaFuncAttributeMaxDynamicSharedMemorySize, SMEM_LY);
    cudaFuncSetAttribute(head_k,       cudaFuncAttributeMaxDynamicSharedMemorySize, SMEM_HD);

    pack_fg<<<NL * 256 * 256 / 256, 256>>>(Wf, Wg);
    pack_r<<<NL * 128 * 128 / 256, 256>>>(Wr);
    pack_t<<<(INCH * HIDC) / 256, 256>>>(p_wip, Wi, HIDC, INCH);
    pack_t<<<(HIDC * MIDC) / 256, 256>>>(p_w1p, W1, MIDC, HIDC);
    pack_t<<<(MIDC * OUTC) / 256, 256>>>(p_w2p, W2, OUTC, MIDC);

    input_conv_k<<<dim3(T0C / 64, NBATCH), 256, SMEM_IC>>>(inputs, bi);

    int Tin = T0C;
    float* rin = p_res0;
    float* rout = p_res1;
    for (int l = 0; l < NL; l++) {
        int d = DIL[l];
        int Tout = Tin - d;
        dim3 grid((Tout + 127) / 128, NBATCH);
        layer_w2<<<grid, 512, SMEM_LY>>>(rin, rout, bf, bg, br, l, d, Tin, Tout, l == 0 ? 1 : 0);
        float* tmp = rin; rin = rout; rout = tmp;
        Tin = Tout;
    }

    head_k<<<dim3((TGT + 31) / 32, NBATCH), 256, SMEM_HD>>>(b1, b2, out);
}

// round 11
// speedup vs baseline: 1.2849x; 1.2849x over previous
#include <cuda_runtime.h>
#include <cuda_fp16.h>
#include <mma.h>
#include <math.h>
#include <cstdint>

using namespace nvcuda;

#define NBATCH 8
#define T0C    8192
#define INCH   256
#define HIDC   128
#define MIDC   512
#define OUTC   256
#define NL     20
#define TGT    6146
#define RST    8192

// ---- fp16 wmma geometry ----
#define XLH    72     // layer/input X tile ld (halfs)
#define DLD    68     // float accumulator staging ld
#define LW1H   264    // GEMM1 weight chunk ld (16 x 256 halfs)
#define LW2H   136    // GEMM2 weight chunk ld (16 x 128 halfs)
#define WBUFH  4224   // halfs per weight buffer (16*264)
#define HLH    40     // head tile ld (halfs)
#define HFD    36     // head float staging ld
#define W1LH   520    // head GEMM1 weight ld
#define W2LH   264    // head GEMM2 weight ld

typedef wmma::fragment<wmma::matrix_a, 16, 16, 16, __half, wmma::col_major> HFragA;
typedef wmma::fragment<wmma::matrix_b, 16, 16, 16, __half, wmma::row_major> HFragB;
typedef wmma::fragment<wmma::accumulator, 16, 16, 16, float> HFragC;

// ---------------- device scratch ----------------
__device__ float  g_res0[(size_t)NBATCH * HIDC * RST];
__device__ float  g_res1[(size_t)NBATCH * HIDC * RST];
__device__ float  g_final[(size_t)NBATCH * HIDC * TGT];
__device__ __half g_WAh[(size_t)NL * 256 * 256];   // [l][k][row], rows 0..127=f, 128..255=g
__device__ __half g_WRh[(size_t)NL * HIDC * HIDC]; // [l][k][o]
__device__ __half g_WiPh[INCH * HIDC];             // [k][o]
__device__ __half g_W1Ph[HIDC * MIDC];             // [k][o]
__device__ __half g_W2Ph[MIDC * OUTC];             // [k][o]

// ---------------- cp.async helpers ----------------
__device__ __forceinline__ uint32_t smem_u32(const void* p) {
    uint32_t a;
    asm("{ .reg .u64 t; cvta.to.shared.u64 t, %1; cvt.u32.u64 %0, t; }" : "=r"(a) : "l"(p));
    return a;
}
#define CP_ASYNC16(dst, src) \
    asm volatile("cp.async.cg.shared.global [%0], [%1], 16;" :: "r"(dst), "l"(src) : "memory")
#define CP_COMMIT() asm volatile("cp.async.commit_group;" ::: "memory")
#define CP_WAIT1()  asm volatile("cp.async.wait_group 1;" ::: "memory")
#define CP_WAIT0()  asm volatile("cp.async.wait_group 0;" ::: "memory")

// ---------------- weight packing (fp32 -> fp16, transposed) ----------------
__global__ void pack_fg(const float* __restrict__ Wf, const float* __restrict__ Wg) {
    int i = blockIdx.x * 256 + threadIdx.x;
    if (i >= NL * 256 * 256) return;
    int row = i & 255;
    int k   = (i >> 8) & 255;
    int l   = i >> 16;
    const float* W = (row < 128) ? Wf : Wg;
    int o = row & 127;
    g_WAh[i] = __float2half(W[(((size_t)l * 128 + o) * 128 + (k & 127)) * 2 + (k >> 7)]);
}
__global__ void pack_r(const float* __restrict__ Wr) {
    int i = blockIdx.x * 256 + threadIdx.x;
    if (i >= NL * 128 * 128) return;
    int o = i & 127;
    int k = (i >> 7) & 127;
    int l = i >> 14;
    g_WRh[i] = __float2half(Wr[((size_t)l * 128 + o) * 128 + k]);
}
__global__ void pack_th(__half* __restrict__ dst, const float* __restrict__ src, int O, int K) {
    int i = blockIdx.x * 256 + threadIdx.x;
    if (i >= O * K) return;
    int o = i % O;
    int k = i / O;
    dst[i] = __float2half(src[o * K + k]);
}

// ---------------- input 1x1 conv (fp16 wmma) ----------------
__global__ __launch_bounds__(256)
void input_conv_h(const float* __restrict__ inp, const float* __restrict__ bi) {
    extern __shared__ float sm[];
    float*  sD  = sm;                                  // 128 x DLD floats
    __half* sXh = (__half*)(sm + 128 * DLD);           // 256 x XLH halfs
    __half* sWh = sXh + 256 * XLH;                     // 16 x LW2H halfs

    int b = blockIdx.y, t0 = blockIdx.x * 64, tid = threadIdx.x, wid = tid >> 5;
    const float* src = inp + (size_t)b * INCH * T0C;

    #pragma unroll 4
    for (int j = 0; j < 64; j++) {
        int idx = j * 256 + tid, row = idx >> 6, col = idx & 63;
        sXh[row * XLH + col] = __float2half(src[(size_t)row * T0C + t0 + col]);
    }

    int m0 = (wid >> 1) * 32, n0 = (wid & 1) * 32;
    HFragC acc[2][2];
    #pragma unroll
    for (int i = 0; i < 2; i++)
        #pragma unroll
        for (int j = 0; j < 2; j++) wmma::fill_fragment(acc[i][j], 0.f);

    for (int c = 0; c < 16; c++) {
        __syncthreads();
        {   // stage 16 x 128 halfs: one 16B unit per thread
            int kc = tid >> 4, off = (tid & 15) * 8;
            *(float4*)(sWh + kc * LW2H + off) =
                *(const float4*)(g_WiPh + (size_t)(c * 16 + kc) * 128 + off);
        }
        __syncthreads();
        HFragA a[2]; HFragB bb[2];
        #pragma unroll
        for (int i = 0; i < 2; i++) wmma::load_matrix_sync(a[i], sWh + m0 + i * 16, LW2H);
        #pragma unroll
        for (int j = 0; j < 2; j++) wmma::load_matrix_sync(bb[j], sXh + (c * 16) * XLH + n0 + j * 16, XLH);
        #pragma unroll
        for (int i = 0; i < 2; i++)
            #pragma unroll
            for (int j = 0; j < 2; j++) wmma::mma_sync(acc[i][j], a[i], bb[j], acc[i][j]);
    }
    #pragma unroll
    for (int i = 0; i < 2; i++)
        #pragma unroll
        for (int j = 0; j < 2; j++)
            wmma::store_matrix_sync(sD + (m0 + i * 16) * DLD + n0 + j * 16, acc[i][j], DLD, wmma::mem_row_major);
    __syncthreads();

    float* dst = g_res0 + (size_t)b * HIDC * RST;
    #pragma unroll 4
    for (int j = 0; j < 32; j++) {
        int idx = j * 256 + tid, row = idx >> 6, col = idx & 63;
        dst[(size_t)row * RST + t0 + col] = sD[row * DLD + col] + bi[row];
    }
}

// ---------------- fused residual layer (fp16 wmma, cp.async 3-buffer pipeline) ----------------
// 256 threads, 64 timesteps/block.
// GEMM1: D1[r, t] = sum_k WA[k, r] * X[k, t], M=256 (f||g), N=64, K=256.
// GEMM2: D2[o, t] = sum_k WR[k, o] * act[k, t], M=128, N=64, K=128.
__global__ __launch_bounds__(256)
void layer_h(const float* __restrict__ rin, float* __restrict__ rout,
             const float* __restrict__ bf, const float* __restrict__ bg,
             const float* __restrict__ br,
             int l, int d, int Tin, int Tout, int first) {
    extern __shared__ float sm[];
    float*  sD  = sm;                                    // 256 x DLD floats (69632 B)
    __half* sXh = (__half*)(sm + 256 * DLD);             // 256 x XLH halfs (36864 B)
    __half* sWb = sXh + 256 * XLH;                       // 3 x WBUFH halfs (25344 B)

    int b = blockIdx.y, t0 = blockIdx.x * 64, tid = threadIdx.x;
    int w = tid >> 5, wM = w >> 1, wN = w & 1;
    const float* src = rin + (size_t)b * HIDC * RST;

    const __half* WAl = g_WAh + (size_t)l * 65536;
    const __half* WRl = g_WRh + (size_t)l * 16384;

    uint32_t wbu[3];
    #pragma unroll
    for (int q = 0; q < 3; q++) wbu[q] = smem_u32(sWb + q * WBUFH);

    // prefetch GEMM1 chunks 0,1 (16 x 256 halfs each; 2 x 16B per thread)
    #pragma unroll
    for (int c = 0; c < 2; c++) {
        const __half* srcw = WAl + c * 4096;
        #pragma unroll
        for (int q = 0; q < 2; q++) {
            int j = q * 256 + tid;
            int kc = j >> 5, off = (j & 31) * 8;
            CP_ASYNC16(wbu[c] + (uint32_t)(kc * LW1H + off) * 2u, srcw + kc * 256 + off);
        }
        CP_COMMIT();
    }

    // stage X (fp16): rows k<128 -> res[k, t], rows k>=128 -> res[k-128, t+d]
    #pragma unroll 4
    for (int it = 0; it < 64; it++) {
        int idx = it * 256 + tid;
        int row = idx >> 6, col = idx & 63;
        int ch = row & 127;
        int tt = t0 + col + ((row >= 128) ? d : 0);
        float v = (tt < Tin) ? src[(size_t)ch * RST + tt] : 0.f;
        sXh[row * XLH + col] = __float2half(v);
    }

    // --- GEMM1: 16 k-chunks, pipelined ---
    int m0 = wM * 64, n0 = wN * 32;
    HFragC acc1[4][2];
    #pragma unroll
    for (int i = 0; i < 4; i++)
        #pragma unroll
        for (int j = 0; j < 2; j++) wmma::fill_fragment(acc1[i][j], 0.f);

    for (int c = 0; c < 16; c++) {
        if (c == 15) { CP_WAIT0(); } else { CP_WAIT1(); }
        __syncthreads();      // chunk c visible; also covers X staging on c==0
        if (c + 2 < 16) {
            const __half* srcw = WAl + (c + 2) * 4096;
            uint32_t dstb = wbu[(c + 2) % 3];
            #pragma unroll
            for (int q = 0; q < 2; q++) {
                int j = q * 256 + tid;
                int kc = j >> 5, off = (j & 31) * 8;
                CP_ASYNC16(dstb + (uint32_t)(kc * LW1H + off) * 2u, srcw + kc * 256 + off);
            }
            CP_COMMIT();
        }
        __half* sW = sWb + (c % 3) * WBUFH;
        HFragA a[4]; HFragB bb[2];
        #pragma unroll
        for (int i = 0; i < 4; i++) wmma::load_matrix_sync(a[i], sW + m0 + i * 16, LW1H);
        #pragma unroll
        for (int j = 0; j < 2; j++) wmma::load_matrix_sync(bb[j], sXh + (c * 16) * XLH + n0 + j * 16, XLH);
        #pragma unroll
        for (int i = 0; i < 4; i++)
            #pragma unroll
            for (int j = 0; j < 2; j++) wmma::mma_sync(acc1[i][j], a[i], bb[j], acc1[i][j]);
    }
    // stage D1 to float smem (no pre-barrier needed: sD untouched so far)
    #pragma unroll
    for (int i = 0; i < 4; i++)
        #pragma unroll
        for (int j = 0; j < 2; j++)
            wmma::store_matrix_sync(sD + (m0 + i * 16) * DLD + n0 + j * 16, acc1[i][j], DLD, wmma::mem_row_major);
    __syncthreads();   // all warps done with GEMM1 (incl. sXh reads) + D1 staged

    // prefetch GEMM2 chunks 0,1 (16 x 128 halfs; 1 x 16B per thread)
    #pragma unroll
    for (int c = 0; c < 2; c++) {
        int kc = tid >> 4, off = (tid & 15) * 8;
        CP_ASYNC16(wbu[c] + (uint32_t)(kc * LW2H + off) * 2u, WRl + (c * 16 + kc) * 128 + off);
        CP_COMMIT();
    }

    // --- activation: act[o][t] = tanh(f+bf)*sigmoid(g+bg) -> fp16, sXh rows 0..127 ---
    const float* bfl = bf + l * 128;
    const float* bgl = bg + l * 128;
    #pragma unroll 4
    for (int it = 0; it < 32; it++) {
        int idx = it * 256 + tid;
        int o = idx >> 6, t = idx & 63;
        float f = tanhf(sD[o * DLD + t] + bfl[o]);
        float g = 1.f / (1.f + expf(-(sD[(128 + o) * DLD + t] + bgl[o])));
        sXh[o * XLH + t] = __float2half(f * g);
    }
    __syncthreads();

    // --- GEMM2: 8 k-chunks, pipelined ---
    int m2 = wM * 32, n2 = wN * 32;
    HFragC acc2[2][2];
    #pragma unroll
    for (int i = 0; i < 2; i++)
        #pragma unroll
        for (int j = 0; j < 2; j++) wmma::fill_fragment(acc2[i][j], 0.f);

    for (int c = 0; c < 8; c++) {
        if (c == 7) { CP_WAIT0(); } else { CP_WAIT1(); }
        __syncthreads();
        if (c + 2 < 8) {
            int kc = tid >> 4, off = (tid & 15) * 8;
            CP_ASYNC16(wbu[(c + 2) % 3] + (uint32_t)(kc * LW2H + off) * 2u,
                       WRl + ((c + 2) * 16 + kc) * 128 + off);
            CP_COMMIT();
        }
        __half* sW = sWb + (c % 3) * WBUFH;
        HFragA a[2]; HFragB bb[2];
        #pragma unroll
        for (int i = 0; i < 2; i++) wmma::load_matrix_sync(a[i], sW + m2 + i * 16, LW2H);
        #pragma unroll
        for (int j = 0; j < 2; j++) wmma::load_matrix_sync(bb[j], sXh + (c * 16) * XLH + n2 + j * 16, XLH);
        #pragma unroll
        for (int i = 0; i < 2; i++)
            #pragma unroll
            for (int j = 0; j < 2; j++) wmma::mma_sync(acc2[i][j], a[i], bb[j], acc2[i][j]);
    }
    __syncthreads();   // all warps done reading sD (activation) + sXh before D2 overwrite of sD
    #pragma unroll
    for (int i = 0; i < 2; i++)
        #pragma unroll
        for (int j = 0; j < 2; j++)
            wmma::store_matrix_sync(sD + (m2 + i * 16) * DLD + n2 + j * 16, acc2[i][j], DLD, wmma::mem_row_major);
    __syncthreads();

    // --- epilogue (fp32): residual re-read from global (L2), skip accumulate ---
    const float* brl = br + l * 128;
    float* dst = rout + (size_t)b * HIDC * RST;
    float* fin = g_final + (size_t)b * HIDC * TGT;
    int off = Tout - TGT;
    #pragma unroll 4
    for (int it = 0; it < 32; it++) {
        int idx = it * 256 + tid;
        int o = idx >> 6, col = idx & 63;
        int t = t0 + col;
        if (t < Tout) {
            float xv = sD[o * DLD + col] + brl[o];
            dst[(size_t)o * RST + t] = xv + src[(size_t)o * RST + t + d];
            int tf = t - off;
            if (tf >= 0) {
                float* p = &fin[(size_t)o * TGT + tf];
                *p = first ? xv : (*p + xv);
            }
        }
    }
}

// ---------------- head (fp16 wmma): relu -> W1 -> relu -> W2 -> transpose ----------------
__global__ __launch_bounds__(256)
void head_h(const float* __restrict__ b1, const float* __restrict__ b2,
            float* __restrict__ out) {
    extern __shared__ float sm[];
    float*  sHf = sm;                                   // 512 x HFD floats (73728 B)
    __half* sFh = (__half*)(sm + 512 * HFD);            // 128 x HLH halfs
    __half* sHh = sFh + 128 * HLH;                      // 512 x HLH halfs
    __half* sWh = sHh + 512 * HLH;                      // 16 x W1LH halfs

    int b = blockIdx.y, t0 = blockIdx.x * 32, tid = threadIdx.x, wid = tid >> 5;
    const float* fin = g_final + (size_t)b * HIDC * TGT;

    #pragma unroll
    for (int j = 0; j < 16; j++) {
        int idx = j * 256 + tid, row = idx >> 5, col = idx & 31;
        int t = t0 + col;
        float v = (t < TGT) ? fmaxf(fin[(size_t)row * TGT + t], 0.f) : 0.f;
        sFh[row * HLH + col] = __float2half(v);
    }

    // --- GEMM h1: [512 x 128] @ [128 x 32]; warp wid rows wid*64..+63 ---
    HFragC a1[4][2];
    #pragma unroll
    for (int i = 0; i < 4; i++)
        #pragma unroll
        for (int j = 0; j < 2; j++) wmma::fill_fragment(a1[i][j], 0.f);

    for (int c = 0; c < 8; c++) {
        __syncthreads();
        {   // stage 16 x 512 halfs: 4 x 16B per thread
            #pragma unroll
            for (int q = 0; q < 4; q++) {
                int j = q * 256 + tid;
                int kc = j >> 6, off = (j & 63) * 8;
                *(float4*)(sWh + kc * W1LH + off) =
                    *(const float4*)(g_W1Ph + (size_t)(c * 16 + kc) * 512 + off);
            }
        }
        __syncthreads();
        HFragA a[4]; HFragB bb[2];
        #pragma unroll
        for (int i = 0; i < 4; i++) wmma::load_matrix_sync(a[i], sWh + wid * 64 + i * 16, W1LH);
        #pragma unroll
        for (int j = 0; j < 2; j++) wmma::load_matrix_sync(bb[j], sFh + (c * 16) * HLH + j * 16, HLH);
        #pragma unroll
        for (int i = 0; i < 4; i++)
            #pragma unroll
            for (int j = 0; j < 2; j++) wmma::mma_sync(a1[i][j], a[i], bb[j], a1[i][j]);
    }
    #pragma unroll
    for (int i = 0; i < 4; i++)
        #pragma unroll
        for (int j = 0; j < 2; j++)
            wmma::store_matrix_sync(sHf + (wid * 64 + i * 16) * HFD + j * 16, a1[i][j], HFD, wmma::mem_row_major);
    __syncthreads();

    // bias + relu -> fp16
    #pragma unroll
    for (int j = 0; j < 64; j++) {
        int idx = j * 256 + tid, r = idx >> 5, c = idx & 31;
        sHh[r * HLH + c] = __float2half(fmaxf(sHf[r * HFD + c] + b1[r], 0.f));
    }

    // --- GEMM out: [256 x 512] @ [512 x 32]; warp wid rows wid*32..+31 ---
    HFragC a2[2][2];
    #pragma unroll
    for (int i = 0; i < 2; i++)
        #pragma unroll
        for (int j = 0; j < 2; j++) wmma::fill_fragment(a2[i][j], 0.f);

    for (int c = 0; c < 32; c++) {
        __syncthreads();
        {   // stage 16 x 256 halfs: 2 x 16B per thread
            #pragma unroll
            for (int q = 0; q < 2; q++) {
                int j = q * 256 + tid;
                int kc = j >> 5, off = (j & 31) * 8;
                *(float4*)(sWh + kc * W2LH + off) =
                    *(const float4*)(g_W2Ph + (size_t)(c * 16 + kc) * 256 + off);
            }
        }
        __syncthreads();
        HFragA a[2]; HFragB bb[2];
        #pragma unroll
        for (int i = 0; i < 2; i++) wmma::load_matrix_sync(a[i], sWh + wid * 32 + i * 16, W2LH);
        #pragma unroll
        for (int j = 0; j < 2; j++) wmma::load_matrix_sync(bb[j], sHh + (c * 16) * HLH + j * 16, HLH);
        #pragma unroll
        for (int i = 0; i < 2; i++)
            #pragma unroll
            for (int j = 0; j < 2; j++) wmma::mma_sync(a2[i][j], a[i], bb[j], a2[i][j]);
    }
    __syncthreads();   // all warps done reading sHf? (sHf rewritten below; act reads finished pre-GEMM2)
    #pragma unroll
    for (int i = 0; i < 2; i++)
        #pragma unroll
        for (int j = 0; j < 2; j++)
            wmma::store_matrix_sync(sHf + (wid * 32 + i * 16) * HFD + j * 16, a2[i][j], HFD, wmma::mem_row_major);
    __syncthreads();

    // transpose out: out[(b*TGT + t)*256 + o]
    #pragma unroll
    for (int j = 0; j < 32; j++) {
        int idx = j * 256 + tid, o = idx & 255, c = idx >> 8;
        int t = t0 + c;
        if (t < TGT)
            out[((size_t)b * TGT + t) * 256 + o] = sHf[o * HFD + c] + b2[o];
    }
}

// ---------------- launch ----------------
static const int DIL[NL] = {1, 2, 4, 8, 16, 32, 64, 128, 256, 512,
                            1, 2, 4, 8, 16, 32, 64, 128, 256, 512};

extern "C" void kernel_launch(void* const* d_in, const int* in_sizes, int n_in,
                              void* d_out, int out_size) {
    const float* inputs = (const float*)d_in[0];
    const float* Wi = (const float*)d_in[1];
    const float* bi = (const float*)d_in[2];
    const float* Wf = (const float*)d_in[3];
    const float* bf = (const float*)d_in[4];
    const float* Wg = (const float*)d_in[5];
    const float* bg = (const float*)d_in[6];
    const float* Wr = (const float*)d_in[7];
    const float* br = (const float*)d_in[8];
    const float* W1 = (const float*)d_in[9];
    const float* b1 = (const float*)d_in[10];
    const float* W2 = (const float*)d_in[11];
    const float* b2 = (const float*)d_in[12];
    float* out = (float*)d_out;

    float *p_res0, *p_res1;
    __half *p_wip, *p_w1p, *p_w2p;
    cudaGetSymbolAddress((void**)&p_res0, g_res0);
    cudaGetSymbolAddress((void**)&p_res1, g_res1);
    cudaGetSymbolAddress((void**)&p_wip, g_WiPh);
    cudaGetSymbolAddress((void**)&p_w1p, g_W1Ph);
    cudaGetSymbolAddress((void**)&p_w2p, g_W2Ph);

    const int SMEM_IC = 128 * DLD * 4 + 256 * XLH * 2 + 16 * LW2H * 2;        // 76032
    const int SMEM_LY = 256 * DLD * 4 + 256 * XLH * 2 + 3 * WBUFH * 2;        // 131840
    const int SMEM_HD = 512 * HFD * 4 + 128 * HLH * 2 + 512 * HLH * 2 + 16 * W1LH * 2; // 141568

    cudaFuncSetAttribute(input_conv_h, cudaFuncAttributeMaxDynamicSharedMemorySize, SMEM_IC);
    cudaFuncSetAttribute(layer_h,      cudaFuncAttributeMaxDynamicSharedMemorySize, SMEM_LY);
    cudaFuncSetAttribute(head_h,       cudaFuncAttributeMaxDynamicSharedMemorySize, SMEM_HD);

    pack_fg<<<NL * 256 * 256 / 256, 256>>>(Wf, Wg);
    pack_r<<<NL * 128 * 128 / 256, 256>>>(Wr);
    pack_th<<<(INCH * HIDC) / 256, 256>>>(p_wip, Wi, HIDC, INCH);
    pack_th<<<(HIDC * MIDC) / 256, 256>>>(p_w1p, W1, MIDC, HIDC);
    pack_th<<<(MIDC * OUTC) / 256, 256>>>(p_w2p, W2, OUTC, MIDC);

    input_conv_h<<<dim3(T0C / 64, NBATCH), 256, SMEM_IC>>>(inputs, bi);

    int Tin = T0C;
    float* rin = p_res0;
    float* rout = p_res1;
    for (int l = 0; l < NL; l++) {
        int d = DIL[l];
        int Tout = Tin - d;
        dim3 grid((Tout + 63) / 64, NBATCH);
        layer_h<<<grid, 256, SMEM_LY>>>(rin, rout, bf, bg, br, l, d, Tin, Tout, l == 0 ? 1 : 0);
        float* tmp = rin; rin = rout; rout = tmp;
        Tin = Tout;
    }

    head_h<<<dim3((TGT + 31) / 32, NBATCH), 256, SMEM_HD>>>(b1, b2, out);
}

// round 14
// speedup vs baseline: 1.5762x; 1.2267x over previous
#include <cuda_runtime.h>
#include <cuda_fp16.h>
#include <mma.h>
#include <math.h>
#include <cstdint>

using namespace nvcuda;

#define NBATCH 8
#define T0C    8192
#define INCH   256
#define HIDC   128
#define MIDC   512
#define OUTC   256
#define NL     20
#define TGT    6146
#define RST    8192

#define K1     288    // GEMM1 contraction: 256 data + 1 ones-row (bias) + 31 zero pad
#define K2     160    // GEMM2 contraction: 128 data + 1 ones-row (bias) + 31 zero pad
#define XLH    72     // X tile ld (halfs)
#define ALD    68     // float accumulator staging ld
#define LW1H   264    // GEMM1 weight chunk ld (halfs)
#define LW2H   136    // GEMM2 weight chunk ld (halfs)
#define WBUFH  8448   // halfs per weight buffer (32*264)

// head / input conv geometry (unchanged from R11)
#define DLD    68
#define HLH    40
#define HFD    36
#define W1LH   520
#define W2LH   264

typedef wmma::fragment<wmma::matrix_a, 16, 16, 16, __half, wmma::col_major> HFragA;
typedef wmma::fragment<wmma::matrix_b, 16, 16, 16, __half, wmma::row_major> HFragB;
typedef wmma::fragment<wmma::accumulator, 16, 16, 16, float> HFragC;

// ---------------- device scratch ----------------
__device__ float  g_res0[(size_t)NBATCH * HIDC * RST];
__device__ float  g_res1[(size_t)NBATCH * HIDC * RST];
__device__ float  g_final[(size_t)NBATCH * HIDC * TGT];
__device__ __half g_WAh[(size_t)NL * K1 * 256];    // [l][k][row]; rows 0..127 f, 128..255 g; k=256 bias row
__device__ __half g_WRh[(size_t)NL * K2 * HIDC];   // [l][k][o]; k=128 bias row
__device__ __half g_WiPh[INCH * HIDC];
__device__ __half g_W1Ph[HIDC * MIDC];
__device__ __half g_W2Ph[MIDC * OUTC];

// ---------------- helpers ----------------
__device__ __forceinline__ uint32_t smem_u32(const void* p) {
    uint32_t a;
    asm("{ .reg .u64 t; cvta.to.shared.u64 t, %1; cvt.u32.u64 %0, t; }" : "=r"(a) : "l"(p));
    return a;
}
#define CP_ASYNC16(dst, src) \
    asm volatile("cp.async.cg.shared.global [%0], [%1], 16;" :: "r"(dst), "l"(src) : "memory")
#define CP_COMMIT() asm volatile("cp.async.commit_group;" ::: "memory")
#define CP_WAIT0()  asm volatile("cp.async.wait_group 0;" ::: "memory")

// ---------------- weight packing ----------------
// g_WAh[(l*K1 + k)*256 + row]
__global__ void pack_fg(const float* __restrict__ Wf, const float* __restrict__ Wg,
                        const float* __restrict__ bf, const float* __restrict__ bg) {
    int bx = blockIdx.x;            // NL * K1 blocks
    int l = bx / K1, k = bx % K1;
    int row = threadIdx.x;          // 256
    float v = 0.f;
    if (k < 256) {
        const float* W = (row < 128) ? Wf : Wg;
        int o = row & 127;
        v = W[(((size_t)l * 128 + o) * 128 + (k & 127)) * 2 + (k >> 7)];
    } else if (k == 256) {
        v = (row < 128) ? bf[l * 128 + row] : bg[l * 128 + (row & 127)];
    }
    g_WAh[((size_t)l * K1 + k) * 256 + row] = __float2half(v);
}
// g_WRh[(l*K2 + k)*128 + o]
__global__ void pack_r(const float* __restrict__ Wr, const float* __restrict__ br) {
    int bx = blockIdx.x;            // NL * K2 blocks
    int l = bx / K2, k = bx % K2;
    int o = threadIdx.x;            // 128
    float v = 0.f;
    if (k < 128)       v = Wr[((size_t)l * 128 + o) * 128 + k];
    else if (k == 128) v = br[l * 128 + o];
    g_WRh[((size_t)l * K2 + k) * 128 + o] = __float2half(v);
}
__global__ void pack_th(__half* __restrict__ dst, const float* __restrict__ src, int O, int K) {
    int i = blockIdx.x * 256 + threadIdx.x;
    if (i >= O * K) return;
    int o = i % O, k = i / O;
    dst[i] = __float2half(src[o * K + k]);
}

// ---------------- input 1x1 conv (fp16 wmma, unchanged) ----------------
__global__ __launch_bounds__(256)
void input_conv_h(const float* __restrict__ inp, const float* __restrict__ bi) {
    extern __shared__ float sm[];
    float*  sD  = sm;
    __half* sXh = (__half*)(sm + 128 * DLD);
    __half* sWh = sXh + 256 * XLH;

    int b = blockIdx.y, t0 = blockIdx.x * 64, tid = threadIdx.x, wid = tid >> 5;
    const float* src = inp + (size_t)b * INCH * T0C;

    #pragma unroll 4
    for (int j = 0; j < 64; j++) {
        int idx = j * 256 + tid, row = idx >> 6, col = idx & 63;
        sXh[row * XLH + col] = __float2half(src[(size_t)row * T0C + t0 + col]);
    }
    int m0 = (wid >> 1) * 32, n0 = (wid & 1) * 32;
    HFragC acc[2][2];
    #pragma unroll
    for (int i = 0; i < 2; i++)
        #pragma unroll
        for (int j = 0; j < 2; j++) wmma::fill_fragment(acc[i][j], 0.f);

    for (int c = 0; c < 16; c++) {
        __syncthreads();
        {
            int kc = tid >> 4, off = (tid & 15) * 8;
            *(float4*)(sWh + kc * LW2H + off) =
                *(const float4*)(g_WiPh + (size_t)(c * 16 + kc) * 128 + off);
        }
        __syncthreads();
        HFragA a[2]; HFragB bb[2];
        #pragma unroll
        for (int i = 0; i < 2; i++) wmma::load_matrix_sync(a[i], sWh + m0 + i * 16, LW2H);
        #pragma unroll
        for (int j = 0; j < 2; j++) wmma::load_matrix_sync(bb[j], sXh + (c * 16) * XLH + n0 + j * 16, XLH);
        #pragma unroll
        for (int i = 0; i < 2; i++)
            #pragma unroll
            for (int j = 0; j < 2; j++) wmma::mma_sync(acc[i][j], a[i], bb[j], acc[i][j]);
    }
    #pragma unroll
    for (int i = 0; i < 2; i++)
        #pragma unroll
        for (int j = 0; j < 2; j++)
            wmma::store_matrix_sync(sD + (m0 + i * 16) * DLD + n0 + j * 16, acc[i][j], DLD, wmma::mem_row_major);
    __syncthreads();

    float* dst = g_res0 + (size_t)b * HIDC * RST;
    #pragma unroll 4
    for (int j = 0; j < 32; j++) {
        int idx = j * 256 + tid, row = idx >> 6, col = idx & 63;
        dst[(size_t)row * RST + t0 + col] = sD[row * DLD + col] + bi[row];
    }
}

// ---------------- fused residual layer ----------------
// 256 threads, 64 ts/block, 2 CTA/SM.
// GEMM1: D1[r,t] = sum_k WA[k,r] * X[k,t], M=256 (f||g), N=64, K=288 (bias folded).
//   Warp w: wN = w>>2 (col group of 32), wR = w&3 (32 f-rows + matching 32 g-rows).
//   Activation fused in registers: act = tanh(f)*sigmoid(g).
// GEMM2: D2[o,t] = sum_k WR[k,o] * act[k,t], M=128, N=64, K=160 (bias folded).
__global__ __launch_bounds__(256, 2)
void layer_h(const float* __restrict__ rin, float* __restrict__ rout,
             int l, int d, int Tin, int Tout, int first) {
    extern __shared__ float sm[];
    float*  sAct = sm;                                  // 128 x ALD floats (34816 B)
    __half* sXh  = (__half*)(sm + 128 * ALD);           // K1 x XLH halfs (41472 B)
    __half* sWb  = sXh + K1 * XLH;                      // 2 x WBUFH halfs (33792 B)

    int b = blockIdx.y, t0 = blockIdx.x * 64, tid = threadIdx.x;
    int w = tid >> 5, wN = w >> 2, wR = w & 3;
    int n0 = wN * 32;
    const float* src = rin + (size_t)b * HIDC * RST;

    const __half* WAl = g_WAh + (size_t)l * K1 * 256;
    const __half* WRl = g_WRh + (size_t)l * K2 * 128;

    uint32_t wbu[2];
    wbu[0] = smem_u32(sWb);
    wbu[1] = smem_u32(sWb + WBUFH);

    // prefetch GEMM1 chunk 0 (32 x 256 halfs; 4 x 16B per thread)
    #pragma unroll
    for (int q = 0; q < 4; q++) {
        int j = q * 256 + tid;
        int kc = j >> 5, off = (j & 31) * 8;
        CP_ASYNC16(wbu[0] + (uint32_t)(kc * LW1H + off) * 2u, WAl + kc * 256 + off);
    }
    CP_COMMIT();

    // stage X (fp16): k<128 -> res[k,t]; 128<=k<256 -> res[k-128,t+d]; k=256 -> 1; k>256 -> 0
    #pragma unroll 4
    for (int it = 0; it < 72; it++) {
        int idx = it * 256 + tid;
        int row = idx >> 6, col = idx & 63;
        float v;
        if (row < 256) {
            int ch = row & 127;
            int tt = t0 + col + ((row >= 128) ? d : 0);
            v = (tt < Tin) ? src[(size_t)ch * RST + tt] : 0.f;
        } else {
            v = (row == 256) ? 1.f : 0.f;
        }
        sXh[row * XLH + col] = __float2half(v);
    }

    // --- GEMM1: 9 k-chunks of 32, 2-buffer cp.async pipeline ---
    HFragC accf[2][2], accg[2][2];
    #pragma unroll
    for (int i = 0; i < 2; i++)
        #pragma unroll
        for (int j = 0; j < 2; j++) { wmma::fill_fragment(accf[i][j], 0.f); wmma::fill_fragment(accg[i][j], 0.f); }

    for (int c = 0; c < 9; c++) {
        CP_WAIT0();
        __syncthreads();     // chunk c visible; first iter also covers X staging
        if (c + 1 < 9) {
            const __half* srcw = WAl + (c + 1) * 32 * 256;
            uint32_t dstb = wbu[(c + 1) & 1];
            #pragma unroll
            for (int q = 0; q < 4; q++) {
                int j = q * 256 + tid;
                int kc = j >> 5, off = (j & 31) * 8;
                CP_ASYNC16(dstb + (uint32_t)(kc * LW1H + off) * 2u, srcw + kc * 256 + off);
            }
            CP_COMMIT();
        }
        __half* sW = sWb + (c & 1) * WBUFH;
        #pragma unroll
        for (int ks = 0; ks < 2; ks++) {
            HFragA af[2], ag[2]; HFragB bb[2];
            #pragma unroll
            for (int i = 0; i < 2; i++) {
                wmma::load_matrix_sync(af[i], sW + ks * 16 * LW1H + wR * 32 + i * 16, LW1H);
                wmma::load_matrix_sync(ag[i], sW + ks * 16 * LW1H + 128 + wR * 32 + i * 16, LW1H);
            }
            #pragma unroll
            for (int j = 0; j < 2; j++)
                wmma::load_matrix_sync(bb[j], sXh + (c * 32 + ks * 16) * XLH + n0 + j * 16, XLH);
            #pragma unroll
            for (int i = 0; i < 2; i++)
                #pragma unroll
                for (int j = 0; j < 2; j++) {
                    wmma::mma_sync(accf[i][j], af[i], bb[j], accf[i][j]);
                    wmma::mma_sync(accg[i][j], ag[i], bb[j], accg[i][j]);
                }
        }
    }

    // --- fused activation in registers: accf <- tanh(accf) * sigmoid(accg) ---
    // (accf/accg tiles share (row,col)->element mapping: same fragment type & shape)
    #pragma unroll
    for (int i = 0; i < 2; i++)
        #pragma unroll
        for (int j = 0; j < 2; j++)
            #pragma unroll
            for (int e = 0; e < accf[i][j].num_elements; e++) {
                float f = tanhf(accf[i][j].x[e]);
                float g = 1.f / (1.f + expf(-accg[i][j].x[e]));
                accf[i][j].x[e] = f * g;
            }
    // stage act (float) to sAct rows wR*32+16i, cols n0+16j  (sAct untouched so far)
    #pragma unroll
    for (int i = 0; i < 2; i++)
        #pragma unroll
        for (int j = 0; j < 2; j++)
            wmma::store_matrix_sync(sAct + (wR * 32 + i * 16) * ALD + n0 + j * 16, accf[i][j], ALD, wmma::mem_row_major);
    __syncthreads();   // all warps: GEMM1 reads of sXh done + act staged

    // prefetch GEMM2 chunk 0 (32 x 128 halfs; 2 x 16B per thread)
    #pragma unroll
    for (int q = 0; q < 2; q++) {
        int j = q * 256 + tid;
        int kc = j >> 4, off = (j & 15) * 8;
        CP_ASYNC16(wbu[0] + (uint32_t)(kc * LW2H + off) * 2u, WRl + kc * 128 + off);
    }
    CP_COMMIT();

    // convert act -> fp16 into sXh rows 0..127; row 128 = ones (bias lane).
    // rows 129..159 keep stale finite data; WR k-rows 129..159 are exactly 0.
    #pragma unroll 4
    for (int it = 0; it < 32; it++) {
        int idx = it * 256 + tid;
        int o = idx >> 6, t = idx & 63;
        sXh[o * XLH + t] = __float2half(sAct[o * ALD + t]);
    }
    if (tid < 64) sXh[128 * XLH + tid] = __float2half(1.f);

    // --- GEMM2: 5 k-chunks of 32, pipelined ---
    HFragC acc2[2][2];
    #pragma unroll
    for (int i = 0; i < 2; i++)
        #pragma unroll
        for (int j = 0; j < 2; j++) wmma::fill_fragment(acc2[i][j], 0.f);

    for (int c = 0; c < 5; c++) {
        CP_WAIT0();
        __syncthreads();     // chunk c + (first iter) act conversion visible
        if (c + 1 < 5) {
            const __half* srcw = WRl + (c + 1) * 32 * 128;
            uint32_t dstb = wbu[(c + 1) & 1];
            #pragma unroll
            for (int q = 0; q < 2; q++) {
                int j = q * 256 + tid;
                int kc = j >> 4, off = (j & 15) * 8;
                CP_ASYNC16(dstb + (uint32_t)(kc * LW2H + off) * 2u, srcw + kc * 128 + off);
            }
            CP_COMMIT();
        }
        __half* sW = sWb + (c & 1) * WBUFH;
        #pragma unroll
        for (int ks = 0; ks < 2; ks++) {
            HFragA a[2]; HFragB bb[2];
            #pragma unroll
            for (int i = 0; i < 2; i++)
                wmma::load_matrix_sync(a[i], sW + ks * 16 * LW2H + wR * 32 + i * 16, LW2H);
            #pragma unroll
            for (int j = 0; j < 2; j++)
                wmma::load_matrix_sync(bb[j], sXh + (c * 32 + ks * 16) * XLH + n0 + j * 16, XLH);
            #pragma unroll
            for (int i = 0; i < 2; i++)
                #pragma unroll
                for (int j = 0; j < 2; j++) wmma::mma_sync(acc2[i][j], a[i], bb[j], acc2[i][j]);
        }
    }
    __syncthreads();   // all warps done reading sAct (none read now) / ensure epilogue order vs stores below
    #pragma unroll
    for (int i = 0; i < 2; i++)
        #pragma unroll
        for (int j = 0; j < 2; j++)
            wmma::store_matrix_sync(sAct + (wR * 32 + i * 16) * ALD + n0 + j * 16, acc2[i][j], ALD, wmma::mem_row_major);
    __syncthreads();

    // --- epilogue (fp32): x already includes br; residual re-read from global; skip accumulate ---
    float* dst = rout + (size_t)b * HIDC * RST;
    float* fin = g_final + (size_t)b * HIDC * TGT;
    int off = Tout - TGT;
    #pragma unroll 4
    for (int it = 0; it < 32; it++) {
        int idx = it * 256 + tid;
        int o = idx >> 6, col = idx & 63;
        int t = t0 + col;
        if (t < Tout) {
            float xv = sAct[o * ALD + col];
            dst[(size_t)o * RST + t] = xv + src[(size_t)o * RST + t + d];
            int tf = t - off;
            if (tf >= 0) {
                float* p = &fin[(size_t)o * TGT + tf];
                *p = first ? xv : (*p + xv);
            }
        }
    }
}

// ---------------- head (fp16 wmma, unchanged) ----------------
__global__ __launch_bounds__(256)
void head_h(const float* __restrict__ b1, const float* __restrict__ b2,
            float* __restrict__ out) {
    extern __shared__ float sm[];
    float*  sHf = sm;
    __half* sFh = (__half*)(sm + 512 * HFD);
    __half* sHh = sFh + 128 * HLH;
    __half* sWh = sHh + 512 * HLH;

    int b = blockIdx.y, t0 = blockIdx.x * 32, tid = threadIdx.x, wid = tid >> 5;
    const float* fin = g_final + (size_t)b * HIDC * TGT;

    #pragma unroll
    for (int j = 0; j < 16; j++) {
        int idx = j * 256 + tid, row = idx >> 5, col = idx & 31;
        int t = t0 + col;
        float v = (t < TGT) ? fmaxf(fin[(size_t)row * TGT + t], 0.f) : 0.f;
        sFh[row * HLH + col] = __float2half(v);
    }
    HFragC a1[4][2];
    #pragma unroll
    for (int i = 0; i < 4; i++)
        #pragma unroll
        for (int j = 0; j < 2; j++) wmma::fill_fragment(a1[i][j], 0.f);

    for (int c = 0; c < 8; c++) {
        __syncthreads();
        #pragma unroll
        for (int q = 0; q < 4; q++) {
            int j = q * 256 + tid;
            int kc = j >> 6, off = (j & 63) * 8;
            *(float4*)(sWh + kc * W1LH + off) =
                *(const float4*)(g_W1Ph + (size_t)(c * 16 + kc) * 512 + off);
        }
        __syncthreads();
        HFragA a[4]; HFragB bb[2];
        #pragma unroll
        for (int i = 0; i < 4; i++) wmma::load_matrix_sync(a[i], sWh + wid * 64 + i * 16, W1LH);
        #pragma unroll
        for (int j = 0; j < 2; j++) wmma::load_matrix_sync(bb[j], sFh + (c * 16) * HLH + j * 16, HLH);
        #pragma unroll
        for (int i = 0; i < 4; i++)
            #pragma unroll
            for (int j = 0; j < 2; j++) wmma::mma_sync(a1[i][j], a[i], bb[j], a1[i][j]);
    }
    #pragma unroll
    for (int i = 0; i < 4; i++)
        #pragma unroll
        for (int j = 0; j < 2; j++)
            wmma::store_matrix_sync(sHf + (wid * 64 + i * 16) * HFD + j * 16, a1[i][j], HFD, wmma::mem_row_major);
    __syncthreads();

    #pragma unroll
    for (int j = 0; j < 64; j++) {
        int idx = j * 256 + tid, r = idx >> 5, c = idx & 31;
        sHh[r * HLH + c] = __float2half(fmaxf(sHf[r * HFD + c] + b1[r], 0.f));
    }

    HFragC a2[2][2];
    #pragma unroll
    for (int i = 0; i < 2; i++)
        #pragma unroll
        for (int j = 0; j < 2; j++) wmma::fill_fragment(a2[i][j], 0.f);

    for (int c = 0; c < 32; c++) {
        __syncthreads();
        #pragma unroll
        for (int q = 0; q < 2; q++) {
            int j = q * 256 + tid;
            int kc = j >> 5, off = (j & 31) * 8;
            *(float4*)(sWh + kc * W2LH + off) =
                *(const float4*)(g_W2Ph + (size_t)(c * 16 + kc) * 256 + off);
        }
        __syncthreads();
        HFragA a[2]; HFragB bb[2];
        #pragma unroll
        for (int i = 0; i < 2; i++) wmma::load_matrix_sync(a[i], sWh + wid * 32 + i * 16, W2LH);
        #pragma unroll
        for (int j = 0; j < 2; j++) wmma::load_matrix_sync(bb[j], sHh + (c * 16) * HLH + j * 16, HLH);
        #pragma unroll
        for (int i = 0; i < 2; i++)
            #pragma unroll
            for (int j = 0; j < 2; j++) wmma::mma_sync(a2[i][j], a[i], bb[j], a2[i][j]);
    }
    __syncthreads();
    #pragma unroll
    for (int i = 0; i < 2; i++)
        #pragma unroll
        for (int j = 0; j < 2; j++)
            wmma::store_matrix_sync(sHf + (wid * 32 + i * 16) * HFD + j * 16, a2[i][j], HFD, wmma::mem_row_major);
    __syncthreads();

    #pragma unroll
    for (int j = 0; j < 32; j++) {
        int idx = j * 256 + tid, o = idx & 255, c = idx >> 8;
        int t = t0 + c;
        if (t < TGT)
            out[((size_t)b * TGT + t) * 256 + o] = sHf[o * HFD + c] + b2[o];
    }
}

// ---------------- launch ----------------
static const int DIL[NL] = {1, 2, 4, 8, 16, 32, 64, 128, 256, 512,
                            1, 2, 4, 8, 16, 32, 64, 128, 256, 512};

extern "C" void kernel_launch(void* const* d_in, const int* in_sizes, int n_in,
                              void* d_out, int out_size) {
    const float* inputs = (const float*)d_in[0];
    const float* Wi = (const float*)d_in[1];
    const float* bi = (const float*)d_in[2];
    const float* Wf = (const float*)d_in[3];
    const float* bf = (const float*)d_in[4];
    const float* Wg = (const float*)d_in[5];
    const float* bg = (const float*)d_in[6];
    const float* Wr = (const float*)d_in[7];
    const float* br = (const float*)d_in[8];
    const float* W1 = (const float*)d_in[9];
    const float* b1 = (const float*)d_in[10];
    const float* W2 = (const float*)d_in[11];
    const float* b2 = (const float*)d_in[12];
    float* out = (float*)d_out;

    float *p_res0, *p_res1;
    __half *p_wip, *p_w1p, *p_w2p;
    cudaGetSymbolAddress((void**)&p_res0, g_res0);
    cudaGetSymbolAddress((void**)&p_res1, g_res1);
    cudaGetSymbolAddress((void**)&p_wip, g_WiPh);
    cudaGetSymbolAddress((void**)&p_w1p, g_W1Ph);
    cudaGetSymbolAddress((void**)&p_w2p, g_W2Ph);

    const int SMEM_IC = 128 * DLD * 4 + 256 * XLH * 2 + 16 * LW2H * 2;         // 76032
    const int SMEM_LY = 128 * ALD * 4 + K1 * XLH * 2 + 2 * WBUFH * 2;          // 110080
    const int SMEM_HD = 512 * HFD * 4 + 128 * HLH * 2 + 512 * HLH * 2 + 16 * W1LH * 2;

    cudaFuncSetAttribute(input_conv_h, cudaFuncAttributeMaxDynamicSharedMemorySize, SMEM_IC);
    cudaFuncSetAttribute(layer_h,      cudaFuncAttributeMaxDynamicSharedMemorySize, SMEM_LY);
    cudaFuncSetAttribute(head_h,       cudaFuncAttributeMaxDynamicSharedMemorySize, SMEM_HD);

    pack_fg<<<NL * K1, 256>>>(Wf, Wg, bf, bg);
    pack_r<<<NL * K2, 128>>>(Wr, br);
    pack_th<<<(INCH * HIDC) / 256, 256>>>(p_wip, Wi, HIDC, INCH);
    pack_th<<<(HIDC * MIDC) / 256, 256>>>(p_w1p, W1, MIDC, HIDC);
    pack_th<<<(MIDC * OUTC) / 256, 256>>>(p_w2p, W2, OUTC, MIDC);

    input_conv_h<<<dim3(T0C / 64, NBATCH), 256, SMEM_IC>>>(inputs, bi);

    int Tin = T0C;
    float* rin = p_res0;
    float* rout = p_res1;
    for (int l = 0; l < NL; l++) {
        int d = DIL[l];
        int Tout = Tin - d;
        dim3 grid((Tout + 63) / 64, NBATCH);
        layer_h<<<grid, 256, SMEM_LY>>>(rin, rout, l, d, Tin, Tout, l == 0 ? 1 : 0);
        float* tmp = rin; rin = rout; rout = tmp;
        Tin = Tout;
    }

    head_h<<<dim3((TGT + 31) / 32, NBATCH), 256, SMEM_HD>>>(b1, b2, out);
}

// round 15
// speedup vs baseline: 1.6987x; 1.0777x over previous
#include <cuda_runtime.h>
#include <cuda_fp16.h>
#include <mma.h>
#include <math.h>
#include <cstdint>

using namespace nvcuda;

#define NBATCH 8
#define T0C    8192
#define INCH   256
#define HIDC   128
#define MIDC   512
#define OUTC   256
#define NL     20
#define TGT    6146
#define RST    8192

#define K1     288    // GEMM1 K: 256 data + 1 ones(bias) + pad
#define K2     160    // GEMM2 K: 128 data + 1 ones(bias) + pad
#define XLH    72
#define ALD    68
#define LW1H   264
#define LW2H   136
#define WBUFH  8448   // halfs per layer weight buffer (32*264)

// input conv geometry
#define DLD    68

// head geometry
#define HK1    144    // W1 K: 128 + ones + pad
#define HK2    528    // W2 K: 512 + ones + pad
#define HFL    72     // F/H tile ld (halfs)
#define HW1LD  520
#define HW2LD  264
#define HWB    16896  // halfs per head weight buffer = max(32*520, 64*264)
#define HTL    68     // float staging ld

typedef wmma::fragment<wmma::matrix_a, 16, 16, 16, __half, wmma::col_major> HFragA;
typedef wmma::fragment<wmma::matrix_b, 16, 16, 16, __half, wmma::row_major> HFragB;
typedef wmma::fragment<wmma::accumulator, 16, 16, 16, float> HFragC;

// ---------------- device scratch ----------------
__device__ float  g_res0[(size_t)NBATCH * HIDC * RST];
__device__ float  g_res1[(size_t)NBATCH * HIDC * RST];
__device__ float  g_final[(size_t)NBATCH * HIDC * TGT];
__device__ __half g_WAh[(size_t)NL * K1 * 256];
__device__ __half g_WRh[(size_t)NL * K2 * HIDC];
__device__ __half g_WiPh[INCH * HIDC];
__device__ __half g_W1Ph[(size_t)HK1 * MIDC];   // [k][o], k=128 bias row
__device__ __half g_W2Ph[(size_t)HK2 * OUTC];   // [k][o], k=512 bias row

// ---------------- helpers ----------------
__device__ __forceinline__ uint32_t smem_u32(const void* p) {
    uint32_t a;
    asm("{ .reg .u64 t; cvta.to.shared.u64 t, %1; cvt.u32.u64 %0, t; }" : "=r"(a) : "l"(p));
    return a;
}
#define CP_ASYNC16(dst, src) \
    asm volatile("cp.async.cg.shared.global [%0], [%1], 16;" :: "r"(dst), "l"(src) : "memory")
#define CP_COMMIT() asm volatile("cp.async.commit_group;" ::: "memory")
#define CP_WAIT0()  asm volatile("cp.async.wait_group 0;" ::: "memory")

// ---------------- fused weight packing (single kernel -> shifts ncu -s onto layer_h) ----------------
#define NWA (NL * K1 * 256)
#define NWR (NL * K2 * 128)
#define NWI (INCH * HIDC)
#define NW1 (HK1 * MIDC)
#define NW2 (HK2 * OUTC)

__global__ void pack_all(const float* __restrict__ Wf, const float* __restrict__ Wg,
                         const float* __restrict__ bf, const float* __restrict__ bg,
                         const float* __restrict__ Wr, const float* __restrict__ br,
                         const float* __restrict__ Wi,
                         const float* __restrict__ W1, const float* __restrict__ b1,
                         const float* __restrict__ W2, const float* __restrict__ b2) {
    int i = blockIdx.x * 256 + threadIdx.x;
    if (i < NWA) {
        int l = i / (K1 * 256), rem = i % (K1 * 256);
        int k = rem >> 8, row = rem & 255;
        float v = 0.f;
        if (k < 256) {
            const float* W = (row < 128) ? Wf : Wg;
            int o = row & 127;
            v = W[(((size_t)l * 128 + o) * 128 + (k & 127)) * 2 + (k >> 7)];
        } else if (k == 256) {
            v = (row < 128) ? bf[l * 128 + row] : bg[l * 128 + (row & 127)];
        }
        g_WAh[i] = __float2half(v);
        return;
    }
    i -= NWA;
    if (i < NWR) {
        int l = i / (K2 * 128), rem = i % (K2 * 128);
        int k = rem >> 7, o = rem & 127;
        float v = 0.f;
        if (k < 128)       v = Wr[((size_t)l * 128 + o) * 128 + k];
        else if (k == 128) v = br[l * 128 + o];
        g_WRh[i] = __float2half(v);
        return;
    }
    i -= NWR;
    if (i < NWI) {
        int o = i & 127, k = i >> 7;
        g_WiPh[i] = __float2half(Wi[o * INCH + k]);
        return;
    }
    i -= NWI;
    if (i < NW1) {
        int k = i / MIDC, o = i % MIDC;
        float v = 0.f;
        if (k < 128)       v = W1[(size_t)o * 128 + k];
        else if (k == 128) v = b1[o];
        g_W1Ph[i] = __float2half(v);
        return;
    }
    i -= NW1;
    if (i < NW2) {
        int k = i / OUTC, o = i % OUTC;
        float v = 0.f;
        if (k < 512)       v = W2[(size_t)o * 512 + k];
        else if (k == 512) v = b2[o];
        g_W2Ph[i] = __float2half(v);
    }
}
#define NPACK (NWA + NWR + NWI + NW1 + NW2)

// ---------------- input 1x1 conv (unchanged) ----------------
__global__ __launch_bounds__(256)
void input_conv_h(const float* __restrict__ inp, const float* __restrict__ bi) {
    extern __shared__ float sm[];
    float*  sD  = sm;
    __half* sXh = (__half*)(sm + 128 * DLD);
    __half* sWh = sXh + 256 * XLH;

    int b = blockIdx.y, t0 = blockIdx.x * 64, tid = threadIdx.x, wid = tid >> 5;
    const float* src = inp + (size_t)b * INCH * T0C;

    #pragma unroll 4
    for (int j = 0; j < 64; j++) {
        int idx = j * 256 + tid, row = idx >> 6, col = idx & 63;
        sXh[row * XLH + col] = __float2half(src[(size_t)row * T0C + t0 + col]);
    }
    int m0 = (wid >> 1) * 32, n0 = (wid & 1) * 32;
    HFragC acc[2][2];
    #pragma unroll
    for (int i = 0; i < 2; i++)
        #pragma unroll
        for (int j = 0; j < 2; j++) wmma::fill_fragment(acc[i][j], 0.f);

    for (int c = 0; c < 16; c++) {
        __syncthreads();
        {
            int kc = tid >> 4, off = (tid & 15) * 8;
            *(float4*)(sWh + kc * LW2H + off) =
                *(const float4*)(g_WiPh + (size_t)(c * 16 + kc) * 128 + off);
        }
        __syncthreads();
        HFragA a[2]; HFragB bb[2];
        #pragma unroll
        for (int i = 0; i < 2; i++) wmma::load_matrix_sync(a[i], sWh + m0 + i * 16, LW2H);
        #pragma unroll
        for (int j = 0; j < 2; j++) wmma::load_matrix_sync(bb[j], sXh + (c * 16) * XLH + n0 + j * 16, XLH);
        #pragma unroll
        for (int i = 0; i < 2; i++)
            #pragma unroll
            for (int j = 0; j < 2; j++) wmma::mma_sync(acc[i][j], a[i], bb[j], acc[i][j]);
    }
    #pragma unroll
    for (int i = 0; i < 2; i++)
        #pragma unroll
        for (int j = 0; j < 2; j++)
            wmma::store_matrix_sync(sD + (m0 + i * 16) * DLD + n0 + j * 16, acc[i][j], DLD, wmma::mem_row_major);
    __syncthreads();

    float* dst = g_res0 + (size_t)b * HIDC * RST;
    #pragma unroll 4
    for (int j = 0; j < 32; j++) {
        int idx = j * 256 + tid, row = idx >> 6, col = idx & 63;
        dst[(size_t)row * RST + t0 + col] = sD[row * DLD + col] + bi[row];
    }
}

// ---------------- fused residual layer ----------------
__global__ __launch_bounds__(256, 2)
void layer_h(const float* __restrict__ rin, float* __restrict__ rout,
             int l, int d, int Tin, int Tout, int first) {
    extern __shared__ float sm[];
    float*  sAct = sm;                                  // 128 x ALD floats
    __half* sXh  = (__half*)(sm + 128 * ALD);           // K1 x XLH halfs
    __half* sWb  = sXh + K1 * XLH;                      // 2 x WBUFH halfs

    int b = blockIdx.y, t0 = blockIdx.x * 64, tid = threadIdx.x;
    int w = tid >> 5, wN = w >> 2, wR = w & 3;
    int n0 = wN * 32, lane = tid & 31;
    const float* src = rin + (size_t)b * HIDC * RST;

    const __half* WAl = g_WAh + (size_t)l * K1 * 256;
    const __half* WRl = g_WRh + (size_t)l * K2 * 128;

    uint32_t wbu[2];
    wbu[0] = smem_u32(sWb);
    wbu[1] = smem_u32(sWb + WBUFH);

    // prefetch GEMM1 chunk 0
    #pragma unroll
    for (int q = 0; q < 4; q++) {
        int j = q * 256 + tid;
        int kc = j >> 5, off = (j & 31) * 8;
        CP_ASYNC16(wbu[0] + (uint32_t)(kc * LW1H + off) * 2u, WAl + kc * 256 + off);
    }
    CP_COMMIT();

    // stage X
    #pragma unroll 4
    for (int it = 0; it < 72; it++) {
        int idx = it * 256 + tid;
        int row = idx >> 6, col = idx & 63;
        float v;
        if (row < 256) {
            int ch = row & 127;
            int tt = t0 + col + ((row >= 128) ? d : 0);
            v = (tt < Tin) ? src[(size_t)ch * RST + tt] : 0.f;
        } else {
            v = (row == 256) ? 1.f : 0.f;
        }
        sXh[row * XLH + col] = __float2half(v);
    }

    // --- GEMM1: 9 k-chunks of 32 ---
    HFragC accf[2][2], accg[2][2];
    #pragma unroll
    for (int i = 0; i < 2; i++)
        #pragma unroll
        for (int j = 0; j < 2; j++) { wmma::fill_fragment(accf[i][j], 0.f); wmma::fill_fragment(accg[i][j], 0.f); }

    for (int c = 0; c < 9; c++) {
        CP_WAIT0();
        __syncthreads();
        if (c + 1 < 9) {
            const __half* srcw = WAl + (c + 1) * 32 * 256;
            uint32_t dstb = wbu[(c + 1) & 1];
            #pragma unroll
            for (int q = 0; q < 4; q++) {
                int j = q * 256 + tid;
                int kc = j >> 5, off = (j & 31) * 8;
                CP_ASYNC16(dstb + (uint32_t)(kc * LW1H + off) * 2u, srcw + kc * 256 + off);
            }
            CP_COMMIT();
        } else {
            // GEMM2 chunk 0 -> buf 1 (free: last used by chunk 7, all warps past its compute)
            #pragma unroll
            for (int q = 0; q < 2; q++) {
                int j = q * 256 + tid;
                int kc = j >> 4, off = (j & 15) * 8;
                CP_ASYNC16(wbu[1] + (uint32_t)(kc * LW2H + off) * 2u, WRl + kc * 128 + off);
            }
            CP_COMMIT();
        }
        __half* sW = sWb + (c & 1) * WBUFH;
        #pragma unroll
        for (int ks = 0; ks < 2; ks++) {
            HFragA af[2], ag[2]; HFragB bb[2];
            #pragma unroll
            for (int i = 0; i < 2; i++) {
                wmma::load_matrix_sync(af[i], sW + ks * 16 * LW1H + wR * 32 + i * 16, LW1H);
                wmma::load_matrix_sync(ag[i], sW + ks * 16 * LW1H + 128 + wR * 32 + i * 16, LW1H);
            }
            #pragma unroll
            for (int j = 0; j < 2; j++)
                wmma::load_matrix_sync(bb[j], sXh + (c * 32 + ks * 16) * XLH + n0 + j * 16, XLH);
            #pragma unroll
            for (int i = 0; i < 2; i++)
                #pragma unroll
                for (int j = 0; j < 2; j++) {
                    wmma::mma_sync(accf[i][j], af[i], bb[j], accf[i][j]);
                    wmma::mma_sync(accg[i][j], ag[i], bb[j], accg[i][j]);
                }
        }
    }

    // --- fused activation in registers ---
    #pragma unroll
    for (int i = 0; i < 2; i++)
        #pragma unroll
        for (int j = 0; j < 2; j++)
            #pragma unroll
            for (int e = 0; e < accf[i][j].num_elements; e++) {
                float f = tanhf(accf[i][j].x[e]);
                float g = 1.f / (1.f + expf(-accg[i][j].x[e]));
                accf[i][j].x[e] = f * g;
            }
    // per-warp: stage own 32x32 region + convert to fp16 (no block barrier needed;
    // rows 0..127 of sXh were only read by GEMM1 chunks 0..3, all warps past chunk 7)
    #pragma unroll
    for (int i = 0; i < 2; i++)
        #pragma unroll
        for (int j = 0; j < 2; j++)
            wmma::store_matrix_sync(sAct + (wR * 32 + i * 16) * ALD + n0 + j * 16, accf[i][j], ALD, wmma::mem_row_major);
    __syncwarp();
    #pragma unroll
    for (int q = 0; q < 32; q++) {
        int e = q * 32 + lane;
        int ro = wR * 32 + (e >> 5), co = n0 + (e & 31);
        sXh[ro * XLH + co] = __float2half(sAct[ro * ALD + co]);
    }
    if (tid < 64) sXh[128 * XLH + tid] = __float2half(1.f);  // bias lane (row 128: GEMM1 done with it)

    // --- GEMM2: 5 k-chunks of 32; chunk c lives in buf (c+1)&1 ---
    HFragC acc2[2][2];
    #pragma unroll
    for (int i = 0; i < 2; i++)
        #pragma unroll
        for (int j = 0; j < 2; j++) wmma::fill_fragment(acc2[i][j], 0.f);

    for (int c = 0; c < 5; c++) {
        CP_WAIT0();
        __syncthreads();
        if (c + 1 < 5) {
            const __half* srcw = WRl + (c + 1) * 32 * 128;
            uint32_t dstb = wbu[c & 1];
            #pragma unroll
            for (int q = 0; q < 2; q++) {
                int j = q * 256 + tid;
                int kc = j >> 4, off = (j & 15) * 8;
                CP_ASYNC16(dstb + (uint32_t)(kc * LW2H + off) * 2u, srcw + kc * 128 + off);
            }
            CP_COMMIT();
        }
        __half* sW = sWb + ((c + 1) & 1) * WBUFH;
        #pragma unroll
        for (int ks = 0; ks < 2; ks++) {
            HFragA a[2]; HFragB bb[2];
            #pragma unroll
            for (int i = 0; i < 2; i++)
                wmma::load_matrix_sync(a[i], sW + ks * 16 * LW2H + wR * 32 + i * 16, LW2H);
            #pragma unroll
            for (int j = 0; j < 2; j++)
                wmma::load_matrix_sync(bb[j], sXh + (c * 32 + ks * 16) * XLH + n0 + j * 16, XLH);
            #pragma unroll
            for (int i = 0; i < 2; i++)
                #pragma unroll
                for (int j = 0; j < 2; j++) wmma::mma_sync(acc2[i][j], a[i], bb[j], acc2[i][j]);
        }
    }
    // store D2 to own sAct region (sAct reads all completed before GEMM2 c=0 barrier)
    #pragma unroll
    for (int i = 0; i < 2; i++)
        #pragma unroll
        for (int j = 0; j < 2; j++)
            wmma::store_matrix_sync(sAct + (wR * 32 + i * 16) * ALD + n0 + j * 16, acc2[i][j], ALD, wmma::mem_row_major);
    __syncthreads();

    // --- epilogue ---
    float* dst = rout + (size_t)b * HIDC * RST;
    float* fin = g_final + (size_t)b * HIDC * TGT;
    int off = Tout - TGT;
    #pragma unroll 4
    for (int it = 0; it < 32; it++) {
        int idx = it * 256 + tid;
        int o = idx >> 6, col = idx & 63;
        int t = t0 + col;
        if (t < Tout) {
            float xv = sAct[o * ALD + col];
            dst[(size_t)o * RST + t] = xv + src[(size_t)o * RST + t + d];
            int tf = t - off;
            if (tf >= 0) {
                float* p = &fin[(size_t)o * TGT + tf];
                *p = first ? xv : (*p + xv);
            }
        }
    }
}

// ---------------- head: pipelined, 64-col tiles, biases folded ----------------
// GEMM h1: H[r,t] = sum_k W1P[k,r] * F[k,t], M=512, N=64, K=144 (b1 via ones row).
// GEMM2:   O[o,t] = sum_k W2P[k,o] * H[k,t], M=256, N=64, K=528 (b2 via ones row).
__global__ __launch_bounds__(256)
void head_h(float* __restrict__ out) {
    extern __shared__ float sm[];
    float*  sTmp = sm;                                   // 8 warps x 16 x HTL floats (34816 B)
    __half* sF   = (__half*)(sm + 8 * 16 * HTL);         // HK1 x HFL (20736 B)
    __half* sHh  = sF + HK1 * HFL;                       // HK2 x HFL (76032 B)
    __half* sWb  = sHh + HK2 * HFL;                      // 2 x HWB (67584 B)
    float*  sOut = (float*)sHh;                          // overlay after GEMM2 (256 x HTL)

    int b = blockIdx.y, t0 = blockIdx.x * 64, tid = threadIdx.x;
    int w = tid >> 5, lane = tid & 31;
    const float* fin = g_final + (size_t)b * HIDC * TGT;

    uint32_t wbu[2];
    wbu[0] = smem_u32(sWb);
    wbu[1] = smem_u32(sWb + HWB);

    // prefetch h1 chunk 0 (32 x 512 halfs)
    #pragma unroll
    for (int q = 0; q < 8; q++) {
        int j = q * 256 + tid;
        int kc = j >> 6, off = (j & 63) * 8;
        CP_ASYNC16(wbu[0] + (uint32_t)(kc * HW1LD + off) * 2u, g_W1Ph + (size_t)kc * 512 + off);
    }
    CP_COMMIT();

    // stage F: rows 0..127 relu(final), 128 ones, 129..143 zero
    #pragma unroll
    for (int it = 0; it < 36; it++) {
        int idx = it * 256 + tid;
        int row = idx >> 6, col = idx & 63;
        float v;
        if (row < 128) {
            int t = t0 + col;
            v = (t < TGT) ? fmaxf(fin[(size_t)row * TGT + t], 0.f) : 0.f;
        } else v = (row == 128) ? 1.f : 0.f;
        sF[row * HFL + col] = __float2half(v);
    }
    // H pad rows: 512 ones, 513..527 zero (never touched again)
    {
        int idx = tid;      // 16 rows x 64 cols = 1024 = 4 x 256
        #pragma unroll
        for (int q = 0; q < 4; q++, idx += 256) {
            int row = 512 + (idx >> 6), col = idx & 63;
            sHh[row * HFL + col] = __float2half((row == 512) ? 1.f : 0.f);
        }
    }

    // --- GEMM h1: 5 chunks (4 x k32 + 1 x k16); warp w -> rows w*64..+63, all 64 cols ---
    HFragC a1[4][4];
    #pragma unroll
    for (int i = 0; i < 4; i++)
        #pragma unroll
        for (int j = 0; j < 4; j++) wmma::fill_fragment(a1[i][j], 0.f);

    for (int c = 0; c < 5; c++) {
        CP_WAIT0();
        __syncthreads();
        if (c + 1 < 5) {
            int rows = (c + 1 < 4) ? 32 : 16;
            const __half* srcw = g_W1Ph + (size_t)(c + 1) * 32 * 512;
            uint32_t dstb = wbu[(c + 1) & 1];
            int nq = rows / 4;   // 8 or 4 cp16 per thread
            for (int q = 0; q < nq; q++) {
                int j = q * 256 + tid;
                int kc = j >> 6, off = (j & 63) * 8;
                CP_ASYNC16(dstb + (uint32_t)(kc * HW1LD + off) * 2u, srcw + (size_t)kc * 512 + off);
            }
            CP_COMMIT();
        } else {
            // GEMM2 chunk 0 -> buf 1
            #pragma unroll
            for (int q = 0; q < 8; q++) {
                int j = q * 256 + tid;
                int kc = j >> 5, off = (j & 31) * 8;
                CP_ASYNC16(wbu[1] + (uint32_t)(kc * HW2LD + off) * 2u, g_W2Ph + (size_t)kc * 256 + off);
            }
            CP_COMMIT();
        }
        __half* sW = sWb + (c & 1) * HWB;
        int nks = (c < 4) ? 2 : 1;
        for (int ks = 0; ks < nks; ks++) {
            HFragA a[4]; HFragB bb[4];
            #pragma unroll
            for (int i = 0; i < 4; i++) wmma::load_matrix_sync(a[i], sW + ks * 16 * HW1LD + w * 64 + i * 16, HW1LD);
            #pragma unroll
            for (int j = 0; j < 4; j++) wmma::load_matrix_sync(bb[j], sF + (c * 32 + ks * 16) * HFL + j * 16, HFL);
            #pragma unroll
            for (int i = 0; i < 4; i++)
                #pragma unroll
                for (int j = 0; j < 4; j++) wmma::mma_sync(a1[i][j], a[i], bb[j], a1[i][j]);
        }
    }

    // per-warp: stage 16 rows at a time -> relu -> fp16 H rows w*64..+63
    float* myTmp = sTmp + w * 16 * HTL;
    #pragma unroll
    for (int i = 0; i < 4; i++) {
        #pragma unroll
        for (int j = 0; j < 4; j++)
            wmma::store_matrix_sync(myTmp + j * 16, a1[i][j], HTL, wmma::mem_row_major);
        __syncwarp();
        int base = w * 64 + i * 16;
        #pragma unroll
        for (int q = 0; q < 32; q++) {
            int e = q * 32 + lane;
            int ro = e >> 6, co = e & 63;
            sHh[(base + ro) * HFL + co] = __float2half(fmaxf(myTmp[ro * HTL + co], 0.f));
        }
        __syncwarp();
    }

    // --- GEMM2: 9 chunks (8 x k64 + 1 x k16); warp w -> rows w*32..+31, 64 cols ---
    HFragC a2[2][4];
    #pragma unroll
    for (int i = 0; i < 2; i++)
        #pragma unroll
        for (int j = 0; j < 4; j++) wmma::fill_fragment(a2[i][j], 0.f);

    for (int c = 0; c < 9; c++) {
        CP_WAIT0();
        __syncthreads();
        if (c + 1 < 9) {
            int rows = (c + 1 < 8) ? 64 : 16;
            const __half* srcw = g_W2Ph + (size_t)(c + 1) * 64 * 256;
            uint32_t dstb = wbu[c & 1];
            int nq = rows / 8;   // 8 or 2 cp16 per thread
            for (int q = 0; q < nq; q++) {
                int j = q * 256 + tid;
                int kc = j >> 5, off = (j & 31) * 8;
                CP_ASYNC16(dstb + (uint32_t)(kc * HW2LD + off) * 2u, srcw + (size_t)kc * 256 + off);
            }
            CP_COMMIT();
        }
        __half* sW = sWb + ((c + 1) & 1) * HWB;
        int nks = (c < 8) ? 4 : 1;
        for (int ks = 0; ks < nks; ks++) {
            HFragA a[2]; HFragB bb[4];
            #pragma unroll
            for (int i = 0; i < 2; i++) wmma::load_matrix_sync(a[i], sW + ks * 16 * HW2LD + w * 32 + i * 16, HW2LD);
            #pragma unroll
            for (int j = 0; j < 4; j++) wmma::load_matrix_sync(bb[j], sHh + (c * 64 + ks * 16) * HFL + j * 16, HFL);
            #pragma unroll
            for (int i = 0; i < 2; i++)
                #pragma unroll
                for (int j = 0; j < 4; j++) wmma::mma_sync(a2[i][j], a[i], bb[j], a2[i][j]);
        }
    }
    __syncthreads();   // all warps done reading sHh before overlay
    #pragma unroll
    for (int i = 0; i < 2; i++)
        #pragma unroll
        for (int j = 0; j < 4; j++)
            wmma::store_matrix_sync(sOut + (w * 32 + i * 16) * HTL + j * 16, a2[i][j], HTL, wmma::mem_row_major);
    __syncthreads();

    // write out transposed (b2 already folded)
    #pragma unroll
    for (int it = 0; it < 64; it++) {
        int idx = it * 256 + tid;
        int o = idx & 255, c = idx >> 8;
        int t = t0 + c;
        if (t < TGT)
            out[((size_t)b * TGT + t) * 256 + o] = sOut[o * HTL + c];
    }
}

// ---------------- launch ----------------
static const int DIL[NL] = {1, 2, 4, 8, 16, 32, 64, 128, 256, 512,
                            1, 2, 4, 8, 16, 32, 64, 128, 256, 512};

extern "C" void kernel_launch(void* const* d_in, const int* in_sizes, int n_in,
                              void* d_out, int out_size) {
    const float* inputs = (const float*)d_in[0];
    const float* Wi = (const float*)d_in[1];
    const float* bi = (const float*)d_in[2];
    const float* Wf = (const float*)d_in[3];
    const float* bf = (const float*)d_in[4];
    const float* Wg = (const float*)d_in[5];
    const float* bg = (const float*)d_in[6];
    const float* Wr = (const float*)d_in[7];
    const float* br = (const float*)d_in[8];
    const float* W1 = (const float*)d_in[9];
    const float* b1 = (const float*)d_in[10];
    const float* W2 = (const float*)d_in[11];
    const float* b2 = (const float*)d_in[12];
    float* out = (float*)d_out;

    float *p_res0, *p_res1;
    cudaGetSymbolAddress((void**)&p_res0, g_res0);
    cudaGetSymbolAddress((void**)&p_res1, g_res1);

    const int SMEM_IC = 128 * DLD * 4 + 256 * XLH * 2 + 16 * LW2H * 2;
    const int SMEM_LY = 128 * ALD * 4 + K1 * XLH * 2 + 2 * WBUFH * 2;
    const int SMEM_HD = 8 * 16 * HTL * 4 + HK1 * HFL * 2 + HK2 * HFL * 2 + 2 * HWB * 2; // 199168

    cudaFuncSetAttribute(input_conv_h, cudaFuncAttributeMaxDynamicSharedMemorySize, SMEM_IC);
    cudaFuncSetAttribute(layer_h,      cudaFuncAttributeMaxDynamicSharedMemorySize, SMEM_LY);
    cudaFuncSetAttribute(head_h,       cudaFuncAttributeMaxDynamicSharedMemorySize, SMEM_HD);

    pack_all<<<(NPACK + 255) / 256, 256>>>(Wf, Wg, bf, bg, Wr, br, Wi, W1, b1, W2, b2);

    input_conv_h<<<dim3(T0C / 64, NBATCH), 256, SMEM_IC>>>(inputs, bi);

    int Tin = T0C;
    float* rin = p_res0;
    float* rout = p_res1;
    for (int l = 0; l < NL; l++) {
        int d = DIL[l];
        int Tout = Tin - d;
        dim3 grid((Tout + 63) / 64, NBATCH);
        layer_h<<<grid, 256, SMEM_LY>>>(rin, rout, l, d, Tin, Tout, l == 0 ? 1 : 0);
        float* tmp = rin; rin = rout; rout = tmp;
        Tin = Tout;
    }

    head_h<<<dim3((TGT + 63) / 64, NBATCH), 256, SMEM_HD>>>(out);
}